// round 1
// baseline (speedup 1.0000x reference)
#include <cuda_runtime.h>

// Problem constants
#define BB   8
#define CC   256
#define HH   128
#define WW   128
#define CRED 64          // C / RED
#define HW   (HH * WW)   // 16384

// Conv tiling
#define TCO      16      // output channels per block
#define TP       32      // 32x32 output pixel tile
#define CICHUNK  8       // input channels staged per smem round

// Scratch (no cudaMalloc allowed): pooled means and SE scales
__device__ float g_pool[BB * CC];
__device__ float g_scale[BB * CC];

// ---------------------------------------------------------------------------
// Conv 3x3, pad 1, NCHW, fp32. Each block: 32x32 pixels x 16 c_out.
// 256 threads; each thread owns a 2x2 pixel patch x 16 c_out = 64 accumulators.
// ---------------------------------------------------------------------------
__global__ __launch_bounds__(256, 2)
void conv3x3_kernel(const float* __restrict__ x,
                    const float* __restrict__ w,
                    const float* __restrict__ bias,
                    float* __restrict__ y)
{
    __shared__ float xs[CICHUNK][TP + 2][TP + 3];   // +3 row stride (odd) to spread banks
    __shared__ float ws[TCO][CICHUNK][9];

    const int b   = blockIdx.z;
    const int co0 = blockIdx.y * TCO;
    const int h0  = (blockIdx.x / (WW / TP)) * TP;
    const int w0  = (blockIdx.x % (WW / TP)) * TP;

    const int tid = threadIdx.x;
    const int tx  = tid & 15;          // 0..15
    const int ty  = tid >> 4;          // 0..15
    const int pi  = ty * 2;            // row base within tile
    const int pj  = tx * 2;            // col base within tile

    float acc[TCO][4];
#pragma unroll
    for (int c = 0; c < TCO; c++)
#pragma unroll
        for (int p = 0; p < 4; p++) acc[c][p] = 0.0f;

    for (int ci0 = 0; ci0 < CC; ci0 += CICHUNK) {
        // Stage input tile (with halo, zero-padded at image borders)
        for (int idx = tid; idx < CICHUNK * (TP + 2) * (TP + 2); idx += 256) {
            int ci = idx / ((TP + 2) * (TP + 2));
            int r  = (idx / (TP + 2)) % (TP + 2);
            int cl = idx % (TP + 2);
            int gh = h0 - 1 + r;
            int gw = w0 - 1 + cl;
            float v = 0.0f;
            if (gh >= 0 && gh < HH && gw >= 0 && gw < WW)
                v = x[(((long)b * CC + ci0 + ci) * HH + gh) * WW + gw];
            xs[ci][r][cl] = v;
        }
        // Stage weights for this (co-tile, ci-chunk)
        for (int idx = tid; idx < TCO * CICHUNK * 9; idx += 256) {
            int co  = idx / (CICHUNK * 9);
            int rem = idx % (CICHUNK * 9);
            int ci  = rem / 9;
            int t   = rem % 9;
            ws[co][ci][t] = w[((long)(co0 + co) * CC + ci0 + ci) * 9 + t];
        }
        __syncthreads();

#pragma unroll
        for (int ci = 0; ci < CICHUNK; ci++) {
#pragma unroll
            for (int kh = 0; kh < 3; kh++) {
#pragma unroll
                for (int kw = 0; kw < 3; kw++) {
                    const float x00 = xs[ci][pi + kh    ][pj + kw    ];
                    const float x01 = xs[ci][pi + kh    ][pj + kw + 1];
                    const float x10 = xs[ci][pi + kh + 1][pj + kw    ];
                    const float x11 = xs[ci][pi + kh + 1][pj + kw + 1];
#pragma unroll
                    for (int c = 0; c < TCO; c++) {
                        const float wv = ws[c][ci][kh * 3 + kw];   // warp-broadcast
                        acc[c][0] = fmaf(x00, wv, acc[c][0]);
                        acc[c][1] = fmaf(x01, wv, acc[c][1]);
                        acc[c][2] = fmaf(x10, wv, acc[c][2]);
                        acc[c][3] = fmaf(x11, wv, acc[c][3]);
                    }
                }
            }
        }
        __syncthreads();
    }

    const int gh = h0 + pi;
    const int gw = w0 + pj;
#pragma unroll
    for (int c = 0; c < TCO; c++) {
        const float bv = bias[co0 + c];
        long base = (((long)b * CC + co0 + c) * HH + gh) * WW + gw;
        y[base]          = acc[c][0] + bv;
        y[base + 1]      = acc[c][1] + bv;
        y[base + WW]     = acc[c][2] + bv;
        y[base + WW + 1] = acc[c][3] + bv;
    }
}

// ---------------------------------------------------------------------------
// Global average pool: one block per (b, c); mean over 16384 pixels.
// ---------------------------------------------------------------------------
__global__ __launch_bounds__(256)
void pool_kernel(const float* __restrict__ y)
{
    const int bc = blockIdx.x;                 // 0..BB*CC-1
    const float4* p = (const float4*)(y + (long)bc * HW);
    float s = 0.0f;
    for (int i = threadIdx.x; i < HW / 4; i += 256) {
        float4 v = p[i];
        s += v.x + v.y + v.z + v.w;
    }
    // warp reduce
#pragma unroll
    for (int o = 16; o > 0; o >>= 1)
        s += __shfl_down_sync(0xFFFFFFFFu, s, o);
    __shared__ float red[8];
    if ((threadIdx.x & 31) == 0) red[threadIdx.x >> 5] = s;
    __syncthreads();
    if (threadIdx.x == 0) {
        float t = 0.0f;
#pragma unroll
        for (int i = 0; i < 8; i++) t += red[i];
        g_pool[bc] = t * (1.0f / HW);
    }
}

// ---------------------------------------------------------------------------
// SE FC stack: tiny, single block.
// ---------------------------------------------------------------------------
__global__ __launch_bounds__(256)
void se_kernel(const float* __restrict__ w1, const float* __restrict__ b1,
               const float* __restrict__ w2, const float* __restrict__ b2)
{
    __shared__ float hbuf[BB][CRED];
    const int tid = threadIdx.x;

    for (int o = tid; o < BB * CRED; o += 256) {
        int b = o / CRED, j = o % CRED;
        float s = b1[j];
        const float* pr = &g_pool[b * CC];
        const float* wr = &w1[j * CC];
        for (int c = 0; c < CC; c++) s = fmaf(pr[c], wr[c], s);
        hbuf[b][j] = fmaxf(s, 0.0f);
    }
    __syncthreads();
    for (int o = tid; o < BB * CC; o += 256) {
        int b = o / CC, c = o % CC;
        float s = b2[c];
        const float* wr = &w2[c * CRED];
#pragma unroll 8
        for (int j = 0; j < CRED; j++) s = fmaf(hbuf[b][j], wr[j], s);
        g_scale[o] = 1.0f / (1.0f + __expf(-s));
    }
}

// ---------------------------------------------------------------------------
// Apply SE scale in place: out[b,c,:,:] *= scale[b,c]. float4 vectorized.
// ---------------------------------------------------------------------------
__global__ __launch_bounds__(256)
void scale_kernel(float* __restrict__ y)
{
    const long i = (long)blockIdx.x * 256 + threadIdx.x;  // float4 index
    const long bc = (i * 4) >> 14;                        // /HW (HW=16384, 4|HW)
    const float sc = g_scale[bc];
    float4* p = (float4*)y;
    float4 v = p[i];
    v.x *= sc; v.y *= sc; v.z *= sc; v.w *= sc;
    p[i] = v;
}

// ---------------------------------------------------------------------------
// Launch: conv -> pool -> SE -> scale. Graph-capturable, allocation-free.
// Inputs (metadata order): x, w_deform, b_deform, w_se1, b_se1, w_se2, b_se2
// ---------------------------------------------------------------------------
extern "C" void kernel_launch(void* const* d_in, const int* in_sizes, int n_in,
                              void* d_out, int out_size)
{
    const float* x  = (const float*)d_in[0];
    const float* wd = (const float*)d_in[1];
    const float* bd = (const float*)d_in[2];
    const float* w1 = (const float*)d_in[3];
    const float* b1 = (const float*)d_in[4];
    const float* w2 = (const float*)d_in[5];
    const float* b2 = (const float*)d_in[6];
    float* out = (float*)d_out;

    dim3 cgrid((HH / TP) * (WW / TP), CC / TCO, BB);   // (16, 16, 8)
    conv3x3_kernel<<<cgrid, 256>>>(x, wd, bd, out);
    pool_kernel<<<BB * CC, 256>>>(out);
    se_kernel<<<1, 256>>>(w1, b1, w2, b2);
    scale_kernel<<<(BB * CC * HW) / 4 / 256, 256>>>(out);
}